// round 15
// baseline (speedup 1.0000x reference)
#include <cuda_runtime.h>

#define TPB 384
#define NB  4         // batches per block
#define NN  29
#define KK  6
#define C1  26
#define UST 27        // u-table stride (odd -> conflict-free scalar LDS)
#define MM  32
#define H2  12
#define EROW 36
#define NROW 36

// ---- dynamic smem layout (float offsets) ----
#define W_WE2  0                      // 26 x 32
#define W_WAB  (W_WE2 + C1*MM)        // 832  [c][a0,a1,a2,b0 | b1,b2,w13,be1]
#define W_BE2  (W_WAB + C1*8)         // 1040
#define W_WG   (W_BE2 + MM)           // 1072
#define W_BG   (W_WG + MM)            // 1104
#define W_WN1F (W_BG + 4)             // 1108
#define W_BN1  (W_WN1F + H2*NROW)     // 1540
#define W_WN2  (W_BN1 + H2)           // 1552
#define W_BN2  (W_WN2 + H2*6)         // 1624
#define W_WM1  (W_BN2 + 8)            // 1632
#define W_BM1  (W_WM1 + 6*MM)         // 1824
#define W_WM2  (W_BM1 + MM)           // 1856
#define W_BM2  (W_WM2 + MM*H2)        // 2240
#define W_WB4  (W_BM2 + 12)           // 2252  [c][b0,b1,b2,w13] for on-the-fly v
#define PBASE  (W_WB4 + C1*4)         // 2356 (mod4==0 -> 16B aligned)
// per-batch scratch (v-table eliminated)
#define P_X    0
#define P_SU   96                     // 32*27 = 864
#define P_SMP  (P_SU + 32*UST)        // 960 (mod4==0 -> float4 aligned)
#define P_SND  (P_SMP + 3*32*EROW)    // 4416
#define P_SNJ  (P_SND + 32*KK)        // 4608
#define PBSZ   (P_SNJ + 32*KK)        // 4800 (mod4==0)
// aliases on dead su region (valid after edge epilogue; 864 >= 608 needed)
#define P_SH12 P_SU
#define P_SFO  (P_SU + 384)
#define P_SHID (P_SU + 576)
#define SMEM_FLOATS (PBASE + NB*PBSZ) // 21556
#define SMEM_BYTES  (SMEM_FLOATS*4)   // 86224

typedef unsigned long long ull;

__device__ __forceinline__ void ffma2(ull& d, ull a, ull b){
    asm("fma.rn.f32x2 %0, %1, %2, %0;" : "+l"(d) : "l"(a), "l"(b));
}
__device__ __forceinline__ ull splat2(float x){
    ull r; asm("mov.b64 %0, {%1, %1};" : "=l"(r) : "f"(x)); return r;
}
__device__ __forceinline__ float2 unpack2(ull v){
    float2 f; asm("mov.b64 {%0, %1}, %2;" : "=f"(f.x), "=f"(f.y) : "l"(v)); return f;
}
__device__ __forceinline__ float ftanh(float v){
    float r; asm("tanh.approx.f32 %0, %1;" : "=f"(r) : "f"(v)); return r;
}
__device__ __forceinline__ float fsigmoid(float v){
    return fmaf(0.5f, ftanh(0.5f*v), 0.5f);
}
__device__ __forceinline__ float fsilu(float v){
    float t = 0.5f*v;
    return fmaf(t, ftanh(t), t);     // v*sigmoid(v)
}

__global__ void __launch_bounds__(TPB, 2)
arnet_kernel(const float* __restrict__ x,
             const float* __restrict__ We1, const float* __restrict__ be1,
             const float* __restrict__ We2, const float* __restrict__ be2,
             const float* __restrict__ Wg,  const float* __restrict__ bgp,
             const float* __restrict__ Wn1, const float* __restrict__ bn1,
             const float* __restrict__ Wn2, const float* __restrict__ bn2,
             const float* __restrict__ Wm1, const float* __restrict__ bm1,
             const float* __restrict__ Wm2, const float* __restrict__ bm2,
             float* __restrict__ out, int Btot)
{
    extern __shared__ float sm[];
    const int tid  = threadIdx.x;
    const int wid  = tid >> 5;
    const int lane = tid & 31;
    const int s    = wid / 3;              // batch slot 0..3
    const int pr   = wid - s*3;            // edge-pair index 0..2
    const int b0   = blockIdx.x * NB;

    float* PB = sm + PBASE + s*PBSZ;

    // ================= staging (once per 4 batches) =================
    for (int t = tid; t < C1*MM; t += TPB) sm[W_WE2 + t] = We2[t];
    for (int t = tid; t < C1*8; t += TPB){
        int c = t >> 3, k = t & 7; float v;
        if (k < 3)       v = We1[k*C1 + c]     + We1[(k+3)*C1 + c];
        else if (k < 6)  v = We1[(k+3)*C1 + c] + We1[(k+6)*C1 + c];
        else if (k == 6) v = We1[12*C1 + c];
        else             v = be1[c];
        sm[W_WAB + t] = v;
    }
    for (int t = tid; t < C1*4; t += TPB){
        int c = t >> 2, k = t & 3;
        sm[W_WB4 + t] = (k < 3) ? (We1[(6+k)*C1 + c] + We1[(9+k)*C1 + c])
                                : We1[12*C1 + c];
    }
    for (int t = tid; t < MM; t += TPB){
        sm[W_BE2 + t] = be2[t]; sm[W_WG + t] = Wg[t]; sm[W_BM1 + t] = bm1[t];
    }
    if (tid == 0) sm[W_BG] = bgp[0];
    for (int t = tid; t < H2*NROW; t += TPB){
        int c = t / NROW, r = t % NROW; float v = 0.0f;
        if (r < 3)       v = Wn1[r*H2 + c] + Wn1[(r+3)*H2 + c];
        else if (r >= 4) v = Wn1[(6 + (r-4))*H2 + c];
        sm[W_WN1F + t] = v;
    }
    for (int t = tid; t < H2; t += TPB){ sm[W_BN1 + t] = bn1[t]; sm[W_BM2 + t] = bm2[t]; }
    for (int t = tid; t < H2*6; t += TPB) sm[W_WN2 + t] = Wn2[t];
    for (int t = tid; t < 8;    t += TPB) sm[W_BN2 + t] = (t < 6) ? bn2[t] : 0.0f;
    for (int t = tid; t < 6*MM; t += TPB) sm[W_WM1 + t] = Wm1[t];
    for (int t = tid; t < MM*H2; t += TPB) sm[W_WM2 + t] = Wm2[t];
    {
        int ss = tid / 96, t2 = tid - ss*96;
        int bb = min(b0 + ss, Btot - 1);
        sm[PBASE + ss*PBSZ + P_X + t2] = (t2 < NN*3) ? x[(size_t)bb*(NN*3) + t2] : 0.0f;
    }
    __syncthreads();

    const float* sxB = PB + P_X;
    const int node = lane;
    const int i    = (node < NN) ? node : (NN-1);   // dummies shadow node 28

    // ================= phase 1 (specialized): KNN | u table =================
    if (pr == 0){
        const float xi0 = sxB[i*3+0], xi1 = sxB[i*3+1], xi2 = sxB[i*3+2];
        float bd[KK]; int bi[KK];
#pragma unroll
        for (int t = 0; t < KK; ++t){ bd[t] = 3.4e38f; bi[t] = 0; }
        for (int j = 0; j < NN; ++j){
            float dx = xi0 - sxB[j*3+0];
            float dy = xi1 - sxB[j*3+1];
            float dz = xi2 - sxB[j*3+2];
            float dd = dx*dx + dy*dy + dz*dz;
            if (dd < bd[KK-1]){
                bd[KK-1] = dd; bi[KK-1] = j;
#pragma unroll
                for (int t = KK-1; t > 0; --t){
                    if (bd[t] < bd[t-1]){
                        float td = bd[t]; bd[t] = bd[t-1]; bd[t-1] = td;
                        int tj = bi[t]; bi[t] = bi[t-1]; bi[t-1] = tj;
                    }
                }
            }
        }
#pragma unroll
        for (int t = 0; t < KK; ++t){
            PB[P_SND + lane*KK + t] = bd[t];
            ((int*)(PB + P_SNJ))[lane*KK + t] = bi[t];
        }
    } else {
        // u table: warp 1 -> c 0..12, warp 2 -> c 13..25
        const float x0 = sxB[lane*3+0], x1 = sxB[lane*3+1], x2 = sxB[lane*3+2];
        const int c0 = (pr == 1) ? 0 : 13;
        const int cE = (pr == 1) ? 13 : C1;
        for (int c = c0; c < cE; ++c){
            const float4* ab = (const float4*)(sm + W_WAB + c*8);
            float4 a = ab[0], bb = ab[1];
            PB[P_SU + lane*UST + c] = bb.w + x0*a.x + x1*a.y + x2*a.z;
        }
    }
    __syncthreads();

    const float dA = PB[P_SND + node*KK + pr*2 + 0];
    const float dB = PB[P_SND + node*KK + pr*2 + 1];
    const int   jA = ((const int*)(PB + P_SNJ))[node*KK + pr*2 + 0];
    const int   jB = ((const int*)(PB + P_SNJ))[node*KK + pr*2 + 1];

    // ================= edge-pair GEMV: on-the-fly v + channel-pair ILP =================
    // Channel mapping invariant: channels (2r, 2r+1) live in mA[r]/mB[r].
    ull mA[16], mB[16];
    {
        const ulonglong2* bp = (const ulonglong2*)(sm + W_BE2);
#pragma unroll
        for (int t = 0; t < 8; ++t){
            ulonglong2 v = bp[t];
            mA[2*t] = v.x; mA[2*t+1] = v.y;
            mB[2*t] = v.x; mB[2*t+1] = v.y;
        }
    }
    {
        const float* ub = PB + P_SU + i*UST;            // stride 27: conflict-free
        const float xA0 = sxB[jA*3+0], xA1 = sxB[jA*3+1], xA2 = sxB[jA*3+2];
        const float xB0 = sxB[jB*3+0], xB1 = sxB[jB*3+1], xB2 = sxB[jB*3+2];
#pragma unroll
        for (int c2 = 0; c2 < 13; ++c2){
            const int c0 = 2*c2, c1 = 2*c2 + 1;
            float uu0 = ub[c0], uu1 = ub[c1];
            float4 wb0 = *(const float4*)(sm + W_WB4 + c0*4);  // broadcast LDS.128
            float4 wb1 = *(const float4*)(sm + W_WB4 + c1*4);  // broadcast LDS.128
            // 4 independent silu chains
            float hA0 = fsilu(fmaf(dA, wb0.w, fmaf(xA2, wb0.z,
                              fmaf(xA1, wb0.y, fmaf(xA0, wb0.x, uu0)))));
            float hB0 = fsilu(fmaf(dB, wb0.w, fmaf(xB2, wb0.z,
                              fmaf(xB1, wb0.y, fmaf(xB0, wb0.x, uu0)))));
            float hA1 = fsilu(fmaf(dA, wb1.w, fmaf(xA2, wb1.z,
                              fmaf(xA1, wb1.y, fmaf(xA0, wb1.x, uu1)))));
            float hB1 = fsilu(fmaf(dB, wb1.w, fmaf(xB2, wb1.z,
                              fmaf(xB1, wb1.y, fmaf(xB0, wb1.x, uu1)))));
            ull hsA0 = splat2(hA0), hsB0 = splat2(hB0);
            ull hsA1 = splat2(hA1), hsB1 = splat2(hB1);
            const ulonglong2* wr0 = (const ulonglong2*)(sm + W_WE2 + c0*MM);
            const ulonglong2* wr1 = (const ulonglong2*)(sm + W_WE2 + c1*MM);
#pragma unroll
            for (int t = 0; t < 8; ++t){
                ulonglong2 w0 = wr0[t];
                ffma2(mA[2*t],   hsA0, w0.x);
                ffma2(mA[2*t+1], hsA0, w0.y);
                ffma2(mB[2*t],   hsB0, w0.x);
                ffma2(mB[2*t+1], hsB0, w0.y);
                ulonglong2 w1 = wr1[t];
                ffma2(mA[2*t],   hsA1, w1.x);
                ffma2(mA[2*t+1], hsA1, w1.y);
                ffma2(mB[2*t],   hsB1, w1.x);
                ffma2(mB[2*t+1], hsB1, w1.y);
            }
        }
    }

    // ---- epilogue: silu + gate (vector Wg), pair-sum, store ----
    {
        float fA[MM], fB[MM];
        float gA = sm[W_BG], gB = gA;
        const float4* wg4 = (const float4*)(sm + W_WG);
#pragma unroll
        for (int q = 0; q < 8; ++q){
            float4 wg = wg4[q];
            float2 fa0 = unpack2(mA[2*q]);
            float2 fa1 = unpack2(mA[2*q+1]);
            float2 fb0 = unpack2(mB[2*q]);
            float2 fb1 = unpack2(mB[2*q+1]);
            float a0 = fsilu(fa0.x), a1 = fsilu(fa0.y), a2 = fsilu(fa1.x), a3 = fsilu(fa1.y);
            float b0v = fsilu(fb0.x), b1v = fsilu(fb0.y), b2v = fsilu(fb1.x), b3v = fsilu(fb1.y);
            gA += a0*wg.x + a1*wg.y + a2*wg.z + a3*wg.w;
            gB += b0v*wg.x + b1v*wg.y + b2v*wg.z + b3v*wg.w;
            fA[4*q+0] = a0; fA[4*q+1] = a1; fA[4*q+2] = a2; fA[4*q+3] = a3;
            fB[4*q+0] = b0v; fB[4*q+1] = b1v; fB[4*q+2] = b2v; fB[4*q+3] = b3v;
        }
        gA = fsigmoid(gA);
        gB = fsigmoid(gB);
        float4* orow = (float4*)(PB + P_SMP + (pr*32 + node)*EROW);
#pragma unroll
        for (int t = 0; t < 8; ++t){
            float4 o;
            o.x = fA[4*t+0]*gA + fB[4*t+0]*gB;
            o.y = fA[4*t+1]*gA + fB[4*t+1]*gB;
            o.z = fA[4*t+2]*gA + fB[4*t+2]*gB;
            o.w = fA[4*t+3]*gA + fB[4*t+3]*gB;
            orow[t] = o;
        }
    }
    __syncthreads();   // P_SMP complete; su region now reusable

    // ================= node MLP: per batch, its 96 threads; trio per node =================
    {
        const int t96   = tid - s*96;       // 0..95 within this batch's warps
        const int node2 = t96 / 3;          // 0..31
        const int t3    = t96 % 3;
        float msum[MM];
        float4* ms4 = (float4*)msum;
#pragma unroll
        for (int t = 0; t < 8; ++t) ms4[t] = make_float4(0.f, 0.f, 0.f, 0.f);
#pragma unroll
        for (int e = 0; e < 3; ++e){
            const float4* rr = (const float4*)(PB + P_SMP + (e*32 + node2)*EROW);
#pragma unroll
            for (int t = 0; t < 8; ++t){
                float4 v = rr[t];
                ms4[t].x += v.x; ms4[t].y += v.y; ms4[t].z += v.z; ms4[t].w += v.w;
            }
        }
        const float y0 = sxB[node2*3+0], y1 = sxB[node2*3+1], y2 = sxB[node2*3+2];
        float h4[4];
#pragma unroll
        for (int k = 0; k < 4; ++k){
            int c = t3*4 + k;
            const float* row = sm + W_WN1F + c*NROW;
            float acc = sm[W_BN1 + c] + y0*row[0] + y1*row[1] + y2*row[2];
            const float4* rw = (const float4*)(row + 4);
#pragma unroll
            for (int t = 0; t < 8; ++t){
                float4 wv = rw[t];
                acc += msum[4*t+0]*wv.x; acc += msum[4*t+1]*wv.y;
                acc += msum[4*t+2]*wv.z; acc += msum[4*t+3]*wv.w;
            }
            h4[k] = fsilu(acc);
        }
        __syncthreads();
#pragma unroll
        for (int k = 0; k < 4; ++k)
            PB[P_SH12 + node2*H2 + t3*4 + k] = h4[k];
        __syncthreads();

        // 12 -> 6 + residual: 2 outputs per trio-thread
        if (node2 < NN){
#pragma unroll
            for (int oo = 0; oo < 2; ++oo){
                int o = t3*2 + oo;
                float acc = sm[W_BN2 + o];
#pragma unroll
                for (int c = 0; c < H2; ++c)
                    acc += PB[P_SH12 + node2*H2 + c] * sm[W_WN2 + c*6 + o];
                float base = (o % 3 == 0) ? y0 : ((o % 3 == 1) ? y1 : y2);
                PB[P_SFO + node2*6 + o] = acc + base;
            }
        }
    }
    __syncthreads();

    // ================= pool + head (warp pr==0 of each batch slot) =================
    if (pr == 0){
        const int pl = lane;
        const int bb = min(b0 + s, Btot - 1);
        float pool[6];
#pragma unroll
        for (int o = 0; o < 6; ++o) pool[o] = (pl < NN) ? PB[P_SFO + pl*6 + o] : 0.0f;
#pragma unroll
        for (int o = 0; o < 6; ++o){
#pragma unroll
            for (int off = 16; off > 0; off >>= 1)
                pool[o] += __shfl_xor_sync(0xffffffffu, pool[o], off);
            pool[o] *= (1.0f / 29.0f);
        }
        float hid = sm[W_BM1 + pl];
#pragma unroll
        for (int c = 0; c < 6; ++c) hid += pool[c] * sm[W_WM1 + c*MM + pl];
        hid = fmaxf(hid, 0.0f);
        PB[P_SHID + pl] = hid;
        __syncwarp();
        if (pl < H2){
            float acc = sm[W_BM2 + pl];
#pragma unroll
            for (int h = 0; h < MM; ++h) acc += PB[P_SHID + h] * sm[W_WM2 + h*H2 + pl];
            out[(size_t)bb*(NN*6) + pl] = acc;
        }
    }
    // zero-fill rows 2..28 for all 4 batches
    for (int t = tid; t < NB*NN*6; t += TPB){
        int ss = t / (NN*6), r = t % (NN*6);
        if (r >= H2){
            int bb = min(b0 + ss, Btot - 1);
            out[(size_t)bb*(NN*6) + r] = 0.0f;
        }
    }
}

extern "C" void kernel_launch(void* const* d_in, const int* in_sizes, int n_in,
                              void* d_out, int out_size)
{
    const float* x   = (const float*)d_in[0];
    // d_in[1] = mask (all-true in this problem)
    const float* We1 = (const float*)d_in[2];
    const float* be1 = (const float*)d_in[3];
    const float* We2 = (const float*)d_in[4];
    const float* be2 = (const float*)d_in[5];
    const float* Wg  = (const float*)d_in[6];
    const float* bg  = (const float*)d_in[7];
    const float* Wn1 = (const float*)d_in[8];
    const float* bn1 = (const float*)d_in[9];
    const float* Wn2 = (const float*)d_in[10];
    const float* bn2 = (const float*)d_in[11];
    const float* Wm1 = (const float*)d_in[12];
    const float* bm1 = (const float*)d_in[13];
    const float* Wm2 = (const float*)d_in[14];
    const float* bm2 = (const float*)d_in[15];

    int B = in_sizes[0] / (NN*3);
    cudaFuncSetAttribute(arnet_kernel, cudaFuncAttributeMaxDynamicSharedMemorySize, SMEM_BYTES);
    int grid = (B + NB - 1) / NB;
    arnet_kernel<<<grid, TPB, SMEM_BYTES>>>(x, We1, be1, We2, be2, Wg, bg,
                                            Wn1, bn1, Wn2, bn2, Wm1, bm1, Wm2, bm2,
                                            (float*)d_out, B);
}

// round 16
// speedup vs baseline: 1.0421x; 1.0421x over previous
#include <cuda_runtime.h>

#define TPB 384
#define NB  4         // batches per block
#define NN  29
#define KK  6
#define C1  26
#define UST 27        // u-table stride (odd -> conflict-free scalar LDS)
#define MM  32
#define H2  12
#define EROW 36
#define NROW 36

// ---- dynamic smem layout (float offsets) ----
#define W_WE2  0                      // 26 x 32
#define W_WAB  (W_WE2 + C1*MM)        // 832  [c][a0,a1,a2,b0 | b1,b2,w13,be1]
#define W_BE2  (W_WAB + C1*8)         // 1040
#define W_WG   (W_BE2 + MM)           // 1072
#define W_BG   (W_WG + MM)            // 1104
#define W_WN1F (W_BG + 4)             // 1108
#define W_BN1  (W_WN1F + H2*NROW)     // 1540
#define W_WN2  (W_BN1 + H2)           // 1552
#define W_BN2  (W_WN2 + H2*6)         // 1624
#define W_WM1  (W_BN2 + 8)            // 1632
#define W_BM1  (W_WM1 + 6*MM)         // 1824
#define W_WM2  (W_BM1 + MM)           // 1856
#define W_BM2  (W_WM2 + MM*H2)        // 2240
#define W_WB4  (W_BM2 + 12)           // 2252  [c][b0,b1,b2,w13] for on-the-fly v
#define PBASE  (W_WB4 + C1*4)         // 2356 (mod4==0 -> 16B aligned)
// per-batch scratch (v-table eliminated)
#define P_X    0
#define P_SU   96                     // 32*27 = 864
#define P_SMP  (P_SU + 32*UST)        // 960 (mod4==0 -> float4 aligned)
#define P_SND  (P_SMP + 3*32*EROW)    // 4416
#define P_SNJ  (P_SND + 32*KK)        // 4608
#define PBSZ   (P_SNJ + 32*KK)        // 4800 (mod4==0)
// aliases on dead su region (valid after edge epilogue; 864 >= 608 needed)
#define P_SH12 P_SU
#define P_SFO  (P_SU + 384)
#define P_SHID (P_SU + 576)
#define SMEM_FLOATS (PBASE + NB*PBSZ) // 21556
#define SMEM_BYTES  (SMEM_FLOATS*4)   // 86224

typedef unsigned long long ull;

__device__ __forceinline__ void ffma2(ull& d, ull a, ull b){
    asm("fma.rn.f32x2 %0, %1, %2, %0;" : "+l"(d) : "l"(a), "l"(b));
}
__device__ __forceinline__ ull splat2(float x){
    ull r; asm("mov.b64 %0, {%1, %1};" : "=l"(r) : "f"(x)); return r;
}
__device__ __forceinline__ float2 unpack2(ull v){
    float2 f; asm("mov.b64 {%0, %1}, %2;" : "=f"(f.x), "=f"(f.y) : "l"(v)); return f;
}
__device__ __forceinline__ float ftanh(float v){
    float r; asm("tanh.approx.f32 %0, %1;" : "=f"(r) : "f"(v)); return r;
}
__device__ __forceinline__ float fsigmoid(float v){
    return fmaf(0.5f, ftanh(0.5f*v), 0.5f);
}
__device__ __forceinline__ float fsilu(float v){
    float t = 0.5f*v;
    return fmaf(t, ftanh(t), t);     // v*sigmoid(v)
}

__global__ void __launch_bounds__(TPB, 2)
arnet_kernel(const float* __restrict__ x,
             const float* __restrict__ We1, const float* __restrict__ be1,
             const float* __restrict__ We2, const float* __restrict__ be2,
             const float* __restrict__ Wg,  const float* __restrict__ bgp,
             const float* __restrict__ Wn1, const float* __restrict__ bn1,
             const float* __restrict__ Wn2, const float* __restrict__ bn2,
             const float* __restrict__ Wm1, const float* __restrict__ bm1,
             const float* __restrict__ Wm2, const float* __restrict__ bm2,
             float* __restrict__ out, int Btot)
{
    extern __shared__ float sm[];
    const int tid  = threadIdx.x;
    const int wid  = tid >> 5;
    const int lane = tid & 31;
    const int s    = wid / 3;              // batch slot 0..3
    const int pr   = wid - s*3;            // edge-pair index 0..2
    const int b0   = blockIdx.x * NB;

    float* PB = sm + PBASE + s*PBSZ;

    // ================= staging (once per 4 batches) =================
    for (int t = tid; t < C1*MM; t += TPB) sm[W_WE2 + t] = We2[t];
    for (int t = tid; t < C1*8; t += TPB){
        int c = t >> 3, k = t & 7; float v;
        if (k < 3)       v = We1[k*C1 + c]     + We1[(k+3)*C1 + c];
        else if (k < 6)  v = We1[(k+3)*C1 + c] + We1[(k+6)*C1 + c];
        else if (k == 6) v = We1[12*C1 + c];
        else             v = be1[c];
        sm[W_WAB + t] = v;
    }
    for (int t = tid; t < C1*4; t += TPB){
        int c = t >> 2, k = t & 3;
        sm[W_WB4 + t] = (k < 3) ? (We1[(6+k)*C1 + c] + We1[(9+k)*C1 + c])
                                : We1[12*C1 + c];
    }
    for (int t = tid; t < MM; t += TPB){
        sm[W_BE2 + t] = be2[t]; sm[W_WG + t] = Wg[t]; sm[W_BM1 + t] = bm1[t];
    }
    if (tid == 0) sm[W_BG] = bgp[0];
    for (int t = tid; t < H2*NROW; t += TPB){
        int c = t / NROW, r = t % NROW; float v = 0.0f;
        if (r < 3)       v = Wn1[r*H2 + c] + Wn1[(r+3)*H2 + c];
        else if (r >= 4) v = Wn1[(6 + (r-4))*H2 + c];
        sm[W_WN1F + t] = v;
    }
    for (int t = tid; t < H2; t += TPB){ sm[W_BN1 + t] = bn1[t]; sm[W_BM2 + t] = bm2[t]; }
    for (int t = tid; t < H2*6; t += TPB) sm[W_WN2 + t] = Wn2[t];
    for (int t = tid; t < 8;    t += TPB) sm[W_BN2 + t] = (t < 6) ? bn2[t] : 0.0f;
    for (int t = tid; t < 6*MM; t += TPB) sm[W_WM1 + t] = Wm1[t];
    for (int t = tid; t < MM*H2; t += TPB) sm[W_WM2 + t] = Wm2[t];
    {
        int ss = tid / 96, t2 = tid - ss*96;
        int bb = min(b0 + ss, Btot - 1);
        sm[PBASE + ss*PBSZ + P_X + t2] = (t2 < NN*3) ? x[(size_t)bb*(NN*3) + t2] : 0.0f;
    }
    __syncthreads();

    const float* sxB = PB + P_X;
    const int node = lane;
    const int i    = (node < NN) ? node : (NN-1);   // dummies shadow node 28

    // ================= phase 1 (specialized): KNN | u table =================
    if (pr == 0){
        const float xi0 = sxB[i*3+0], xi1 = sxB[i*3+1], xi2 = sxB[i*3+2];
        float bd[KK]; int bi[KK];
#pragma unroll
        for (int t = 0; t < KK; ++t){ bd[t] = 3.4e38f; bi[t] = 0; }
        for (int j = 0; j < NN; ++j){
            float dx = xi0 - sxB[j*3+0];
            float dy = xi1 - sxB[j*3+1];
            float dz = xi2 - sxB[j*3+2];
            float dd = dx*dx + dy*dy + dz*dz;
            if (dd < bd[KK-1]){
                bd[KK-1] = dd; bi[KK-1] = j;
#pragma unroll
                for (int t = KK-1; t > 0; --t){
                    if (bd[t] < bd[t-1]){
                        float td = bd[t]; bd[t] = bd[t-1]; bd[t-1] = td;
                        int tj = bi[t]; bi[t] = bi[t-1]; bi[t-1] = tj;
                    }
                }
            }
        }
#pragma unroll
        for (int t = 0; t < KK; ++t){
            PB[P_SND + lane*KK + t] = bd[t];
            ((int*)(PB + P_SNJ))[lane*KK + t] = bi[t];
        }
    } else {
        // u table: warp 1 -> c 0..12, warp 2 -> c 13..25
        const float x0 = sxB[lane*3+0], x1 = sxB[lane*3+1], x2 = sxB[lane*3+2];
        const int c0 = (pr == 1) ? 0 : 13;
        const int cE = (pr == 1) ? 13 : C1;
        for (int c = c0; c < cE; ++c){
            const float4* ab = (const float4*)(sm + W_WAB + c*8);
            float4 a = ab[0], bb = ab[1];
            PB[P_SU + lane*UST + c] = bb.w + x0*a.x + x1*a.y + x2*a.z;
        }
    }
    __syncthreads();

    const float dA = PB[P_SND + node*KK + pr*2 + 0];
    const float dB = PB[P_SND + node*KK + pr*2 + 1];
    const int   jA = ((const int*)(PB + P_SNJ))[node*KK + pr*2 + 0];
    const int   jB = ((const int*)(PB + P_SNJ))[node*KK + pr*2 + 1];

    // ================= edge-pair GEMV: v computed on the fly =================
    // Channel mapping invariant: channels (2r, 2r+1) live in mA[r]/mB[r].
    ull mA[16], mB[16];
    {
        const ulonglong2* bp = (const ulonglong2*)(sm + W_BE2);
#pragma unroll
        for (int t = 0; t < 8; ++t){
            ulonglong2 v = bp[t];
            mA[2*t] = v.x; mA[2*t+1] = v.y;
            mB[2*t] = v.x; mB[2*t+1] = v.y;
        }
    }
    {
        const float* ub = PB + P_SU + i*UST;            // stride 27: conflict-free
        const float xA0 = sxB[jA*3+0], xA1 = sxB[jA*3+1], xA2 = sxB[jA*3+2];
        const float xB0 = sxB[jB*3+0], xB1 = sxB[jB*3+1], xB2 = sxB[jB*3+2];
#pragma unroll
        for (int c = 0; c < C1; ++c){
            float uu = ub[c];
            float4 wb = *(const float4*)(sm + W_WB4 + c*4);   // broadcast LDS.128
            float hA = fsilu(fmaf(dA, wb.w, fmaf(xA2, wb.z,
                             fmaf(xA1, wb.y, fmaf(xA0, wb.x, uu)))));
            float hB = fsilu(fmaf(dB, wb.w, fmaf(xB2, wb.z,
                             fmaf(xB1, wb.y, fmaf(xB0, wb.x, uu)))));
            ull hsA = splat2(hA);
            ull hsB = splat2(hB);
            const ulonglong2* wr = (const ulonglong2*)(sm + W_WE2 + c*MM);
#pragma unroll
            for (int t = 0; t < 8; ++t){
                ulonglong2 ww = wr[t];
                ffma2(mA[2*t],   hsA, ww.x);
                ffma2(mA[2*t+1], hsA, ww.y);
                ffma2(mB[2*t],   hsB, ww.x);
                ffma2(mB[2*t+1], hsB, ww.y);
            }
        }
    }

    // ---- epilogue: silu + gate (vector Wg), pair-sum, store ----
    {
        float fA[MM], fB[MM];
        float gA = sm[W_BG], gB = gA;
        const float4* wg4 = (const float4*)(sm + W_WG);
#pragma unroll
        for (int q = 0; q < 8; ++q){
            float4 wg = wg4[q];
            float2 fa0 = unpack2(mA[2*q]);
            float2 fa1 = unpack2(mA[2*q+1]);
            float2 fb0 = unpack2(mB[2*q]);
            float2 fb1 = unpack2(mB[2*q+1]);
            float a0 = fsilu(fa0.x), a1 = fsilu(fa0.y), a2 = fsilu(fa1.x), a3 = fsilu(fa1.y);
            float b0v = fsilu(fb0.x), b1v = fsilu(fb0.y), b2v = fsilu(fb1.x), b3v = fsilu(fb1.y);
            gA += a0*wg.x + a1*wg.y + a2*wg.z + a3*wg.w;
            gB += b0v*wg.x + b1v*wg.y + b2v*wg.z + b3v*wg.w;
            fA[4*q+0] = a0; fA[4*q+1] = a1; fA[4*q+2] = a2; fA[4*q+3] = a3;
            fB[4*q+0] = b0v; fB[4*q+1] = b1v; fB[4*q+2] = b2v; fB[4*q+3] = b3v;
        }
        gA = fsigmoid(gA);
        gB = fsigmoid(gB);
        float4* orow = (float4*)(PB + P_SMP + (pr*32 + node)*EROW);
#pragma unroll
        for (int t = 0; t < 8; ++t){
            float4 o;
            o.x = fA[4*t+0]*gA + fB[4*t+0]*gB;
            o.y = fA[4*t+1]*gA + fB[4*t+1]*gB;
            o.z = fA[4*t+2]*gA + fB[4*t+2]*gB;
            o.w = fA[4*t+3]*gA + fB[4*t+3]*gB;
            orow[t] = o;
        }
    }
    __syncthreads();   // P_SMP complete; su region now reusable

    // ================= node MLP: per batch, its 96 threads; trio per node =================
    {
        const int t96   = tid - s*96;       // 0..95 within this batch's warps
        const int node2 = t96 / 3;          // 0..31
        const int t3    = t96 % 3;
        float msum[MM];
        float4* ms4 = (float4*)msum;
#pragma unroll
        for (int t = 0; t < 8; ++t) ms4[t] = make_float4(0.f, 0.f, 0.f, 0.f);
#pragma unroll
        for (int e = 0; e < 3; ++e){
            const float4* rr = (const float4*)(PB + P_SMP + (e*32 + node2)*EROW);
#pragma unroll
            for (int t = 0; t < 8; ++t){
                float4 v = rr[t];
                ms4[t].x += v.x; ms4[t].y += v.y; ms4[t].z += v.z; ms4[t].w += v.w;
            }
        }
        const float y0 = sxB[node2*3+0], y1 = sxB[node2*3+1], y2 = sxB[node2*3+2];
        float h4[4];
#pragma unroll
        for (int k = 0; k < 4; ++k){
            int c = t3*4 + k;
            const float* row = sm + W_WN1F + c*NROW;
            float acc = sm[W_BN1 + c] + y0*row[0] + y1*row[1] + y2*row[2];
            const float4* rw = (const float4*)(row + 4);
#pragma unroll
            for (int t = 0; t < 8; ++t){
                float4 wv = rw[t];
                acc += msum[4*t+0]*wv.x; acc += msum[4*t+1]*wv.y;
                acc += msum[4*t+2]*wv.z; acc += msum[4*t+3]*wv.w;
            }
            h4[k] = fsilu(acc);
        }
        __syncthreads();
#pragma unroll
        for (int k = 0; k < 4; ++k)
            PB[P_SH12 + node2*H2 + t3*4 + k] = h4[k];
        __syncthreads();

        // 12 -> 6 + residual: 2 outputs per trio-thread
        if (node2 < NN){
#pragma unroll
            for (int oo = 0; oo < 2; ++oo){
                int o = t3*2 + oo;
                float acc = sm[W_BN2 + o];
#pragma unroll
                for (int c = 0; c < H2; ++c)
                    acc += PB[P_SH12 + node2*H2 + c] * sm[W_WN2 + c*6 + o];
                float base = (o % 3 == 0) ? y0 : ((o % 3 == 1) ? y1 : y2);
                PB[P_SFO + node2*6 + o] = acc + base;
            }
        }
    }
    __syncthreads();

    // ================= pool + head (warp pr==0 of each batch slot) =================
    if (pr == 0){
        const int pl = lane;
        const int bb = min(b0 + s, Btot - 1);
        float pool[6];
#pragma unroll
        for (int o = 0; o < 6; ++o) pool[o] = (pl < NN) ? PB[P_SFO + pl*6 + o] : 0.0f;
#pragma unroll
        for (int o = 0; o < 6; ++o){
#pragma unroll
            for (int off = 16; off > 0; off >>= 1)
                pool[o] += __shfl_xor_sync(0xffffffffu, pool[o], off);
            pool[o] *= (1.0f / 29.0f);
        }
        float hid = sm[W_BM1 + pl];
#pragma unroll
        for (int c = 0; c < 6; ++c) hid += pool[c] * sm[W_WM1 + c*MM + pl];
        hid = fmaxf(hid, 0.0f);
        PB[P_SHID + pl] = hid;
        __syncwarp();
        if (pl < H2){
            float acc = sm[W_BM2 + pl];
#pragma unroll
            for (int h = 0; h < MM; ++h) acc += PB[P_SHID + h] * sm[W_WM2 + h*H2 + pl];
            out[(size_t)bb*(NN*6) + pl] = acc;
        }
    }
    // zero-fill rows 2..28 for all 4 batches
    for (int t = tid; t < NB*NN*6; t += TPB){
        int ss = t / (NN*6), r = t % (NN*6);
        if (r >= H2){
            int bb = min(b0 + ss, Btot - 1);
            out[(size_t)bb*(NN*6) + r] = 0.0f;
        }
    }
}

extern "C" void kernel_launch(void* const* d_in, const int* in_sizes, int n_in,
                              void* d_out, int out_size)
{
    const float* x   = (const float*)d_in[0];
    // d_in[1] = mask (all-true in this problem)
    const float* We1 = (const float*)d_in[2];
    const float* be1 = (const float*)d_in[3];
    const float* We2 = (const float*)d_in[4];
    const float* be2 = (const float*)d_in[5];
    const float* Wg  = (const float*)d_in[6];
    const float* bg  = (const float*)d_in[7];
    const float* Wn1 = (const float*)d_in[8];
    const float* bn1 = (const float*)d_in[9];
    const float* Wn2 = (const float*)d_in[10];
    const float* bn2 = (const float*)d_in[11];
    const float* Wm1 = (const float*)d_in[12];
    const float* bm1 = (const float*)d_in[13];
    const float* Wm2 = (const float*)d_in[14];
    const float* bm2 = (const float*)d_in[15];

    int B = in_sizes[0] / (NN*3);
    cudaFuncSetAttribute(arnet_kernel, cudaFuncAttributeMaxDynamicSharedMemorySize, SMEM_BYTES);
    int grid = (B + NB - 1) / NB;
    arnet_kernel<<<grid, TPB, SMEM_BYTES>>>(x, We1, be1, We2, be2, Wg, bg,
                                            Wn1, bn1, Wn2, bn2, Wm1, bm1, Wm2, bm2,
                                            (float*)d_out, B);
}

// round 17
// speedup vs baseline: 1.3823x; 1.3264x over previous
#include <cuda_runtime.h>

#define TPB 384
#define NB  4         // batches per block
#define NN  29
#define KK  6
#define C1  26
#define UST 27        // u-table stride (odd -> conflict-free scalar LDS)
#define MM  32
#define H2  12
#define EROW 36
#define NROW 36

// ---- constant-memory weight tables (broadcast reads -> constant port, not LSU) ----
__constant__ __align__(16) float cWE2[C1*MM];   // raw We2 [26][32]
__constant__ __align__(16) float cWB4[C1*4];    // folded [c][b0,b1,b2,w13]
__constant__ __align__(16) float cBE2[MM];
__constant__ __align__(16) float cWG[MM];
__constant__ float cBG[1];
__device__   float g_wb4[C1*4];                 // prep scratch (static, no alloc)

// ---- dynamic smem layout (float offsets) ----
#define W_WAB  0                      // 208  [c][a0,a1,a2,b0 | b1,b2,w13,be1]
#define W_WN1F (W_WAB + C1*8)         // 208
#define W_BN1  (W_WN1F + H2*NROW)     // 640
#define W_WN2  (W_BN1 + H2)           // 652
#define W_BN2  (W_WN2 + H2*6)         // 724
#define W_WM1  (W_BN2 + 8)            // 732
#define W_BM1  (W_WM1 + 6*MM)         // 924
#define W_BM2  (W_BM1 + MM)           // 956
#define W_WM2  (W_BM2 + H2)           // 968
#define PBASE  (W_WM2 + MM*H2)        // 1352 (mod4==0 -> 16B aligned)
// per-batch scratch
#define P_X    0
#define P_SU   96                     // 32*27 = 864
#define P_SMP  (P_SU + 32*UST)        // 960 (mod4==0 -> float4 aligned)
#define P_SND  (P_SMP + 3*32*EROW)    // 4416
#define P_SNJ  (P_SND + 32*KK)        // 4608
#define PBSZ   (P_SNJ + 32*KK)        // 4800 (mod4==0)
// aliases on dead su region (valid after edge epilogue)
#define P_SH12 P_SU
#define P_SFO  (P_SU + 384)
#define P_SHID (P_SU + 576)
#define SMEM_FLOATS (PBASE + NB*PBSZ) // 20552
#define SMEM_BYTES  (SMEM_FLOATS*4)   // 82208

typedef unsigned long long ull;

__device__ __forceinline__ void ffma2(ull& d, ull a, ull b){
    asm("fma.rn.f32x2 %0, %1, %2, %0;" : "+l"(d) : "l"(a), "l"(b));
}
__device__ __forceinline__ ull splat2(float x){
    ull r; asm("mov.b64 %0, {%1, %1};" : "=l"(r) : "f"(x)); return r;
}
__device__ __forceinline__ float2 unpack2(ull v){
    float2 f; asm("mov.b64 {%0, %1}, %2;" : "=f"(f.x), "=f"(f.y) : "l"(v)); return f;
}
__device__ __forceinline__ float ftanh(float v){
    float r; asm("tanh.approx.f32 %0, %1;" : "=f"(r) : "f"(v)); return r;
}
__device__ __forceinline__ float fsigmoid(float v){
    return fmaf(0.5f, ftanh(0.5f*v), 0.5f);
}
__device__ __forceinline__ float fsilu(float v){
    float t = 0.5f*v;
    return fmaf(t, ftanh(t), t);     // v*sigmoid(v)
}

// prep: fold We1 rows 6..11 (+ row 12) into WB4 layout [c][b0,b1,b2,w13]
__global__ void arnet_prep(const float* __restrict__ We1){
    int t = threadIdx.x;
    if (t < C1*4){
        int c = t >> 2, k = t & 3;
        g_wb4[t] = (k < 3) ? (We1[(6+k)*C1 + c] + We1[(9+k)*C1 + c])
                           : We1[12*C1 + c];
    }
}

__global__ void __launch_bounds__(TPB, 2)
arnet_kernel(const float* __restrict__ x,
             const float* __restrict__ We1, const float* __restrict__ be1,
             const float* __restrict__ Wn1, const float* __restrict__ bn1,
             const float* __restrict__ Wn2, const float* __restrict__ bn2,
             const float* __restrict__ Wm1, const float* __restrict__ bm1,
             const float* __restrict__ Wm2, const float* __restrict__ bm2,
             float* __restrict__ out, int Btot)
{
    extern __shared__ float sm[];
    const int tid  = threadIdx.x;
    const int wid  = tid >> 5;
    const int lane = tid & 31;
    const int s    = wid / 3;              // batch slot 0..3
    const int pr   = wid - s*3;            // edge-pair index 0..2
    const int b0   = blockIdx.x * NB;

    float* PB = sm + PBASE + s*PBSZ;

    // ================= staging (once per 4 batches) =================
    for (int t = tid; t < C1*8; t += TPB){
        int c = t >> 3, k = t & 7; float v;
        if (k < 3)       v = We1[k*C1 + c]     + We1[(k+3)*C1 + c];
        else if (k < 6)  v = We1[(k+3)*C1 + c] + We1[(k+6)*C1 + c];
        else if (k == 6) v = We1[12*C1 + c];
        else             v = be1[c];
        sm[W_WAB + t] = v;
    }
    for (int t = tid; t < H2*NROW; t += TPB){
        int c = t / NROW, r = t % NROW; float v = 0.0f;
        if (r < 3)       v = Wn1[r*H2 + c] + Wn1[(r+3)*H2 + c];
        else if (r >= 4) v = Wn1[(6 + (r-4))*H2 + c];
        sm[W_WN1F + t] = v;
    }
    for (int t = tid; t < H2; t += TPB){ sm[W_BN1 + t] = bn1[t]; sm[W_BM2 + t] = bm2[t]; }
    for (int t = tid; t < H2*6; t += TPB) sm[W_WN2 + t] = Wn2[t];
    for (int t = tid; t < 8;    t += TPB) sm[W_BN2 + t] = (t < 6) ? bn2[t] : 0.0f;
    for (int t = tid; t < 6*MM; t += TPB) sm[W_WM1 + t] = Wm1[t];
    for (int t = tid; t < MM;   t += TPB) sm[W_BM1 + t] = bm1[t];
    for (int t = tid; t < MM*H2; t += TPB) sm[W_WM2 + t] = Wm2[t];
    {
        int ss = tid / 96, t2 = tid - ss*96;
        int bb = min(b0 + ss, Btot - 1);
        sm[PBASE + ss*PBSZ + P_X + t2] = (t2 < NN*3) ? x[(size_t)bb*(NN*3) + t2] : 0.0f;
    }
    __syncthreads();

    const float* sxB = PB + P_X;
    const int node = lane;
    const int i    = (node < NN) ? node : (NN-1);   // dummies shadow node 28

    // ================= phase 1 (specialized): KNN | u table =================
    if (pr == 0){
        const float xi0 = sxB[i*3+0], xi1 = sxB[i*3+1], xi2 = sxB[i*3+2];
        float bd[KK]; int bi[KK];
#pragma unroll
        for (int t = 0; t < KK; ++t){ bd[t] = 3.4e38f; bi[t] = 0; }
        for (int j = 0; j < NN; ++j){
            float dx = xi0 - sxB[j*3+0];
            float dy = xi1 - sxB[j*3+1];
            float dz = xi2 - sxB[j*3+2];
            float dd = dx*dx + dy*dy + dz*dz;
            if (dd < bd[KK-1]){
                bd[KK-1] = dd; bi[KK-1] = j;
#pragma unroll
                for (int t = KK-1; t > 0; --t){
                    if (bd[t] < bd[t-1]){
                        float td = bd[t]; bd[t] = bd[t-1]; bd[t-1] = td;
                        int tj = bi[t]; bi[t] = bi[t-1]; bi[t-1] = tj;
                    }
                }
            }
        }
#pragma unroll
        for (int t = 0; t < KK; ++t){
            PB[P_SND + lane*KK + t] = bd[t];
            ((int*)(PB + P_SNJ))[lane*KK + t] = bi[t];
        }
    } else {
        // u table: warp 1 -> c 0..12, warp 2 -> c 13..25
        const float x0 = sxB[lane*3+0], x1 = sxB[lane*3+1], x2 = sxB[lane*3+2];
        const int c0 = (pr == 1) ? 0 : 13;
        const int cE = (pr == 1) ? 13 : C1;
        for (int c = c0; c < cE; ++c){
            const float4* ab = (const float4*)(sm + W_WAB + c*8);
            float4 a = ab[0], bb = ab[1];
            PB[P_SU + lane*UST + c] = bb.w + x0*a.x + x1*a.y + x2*a.z;
        }
    }
    __syncthreads();

    const float dA = PB[P_SND + node*KK + pr*2 + 0];
    const float dB = PB[P_SND + node*KK + pr*2 + 1];
    const int   jA = ((const int*)(PB + P_SNJ))[node*KK + pr*2 + 0];
    const int   jB = ((const int*)(PB + P_SNJ))[node*KK + pr*2 + 1];

    // ================= edge-pair GEMV: weights from constant memory =================
    // Channel mapping invariant: channels (2r, 2r+1) live in mA[r]/mB[r].
    ull mA[16], mB[16];
    {
        const ulonglong2* bp = (const ulonglong2*)(const void*)cBE2;
#pragma unroll
        for (int t = 0; t < 8; ++t){
            ulonglong2 v = bp[t];
            mA[2*t] = v.x; mA[2*t+1] = v.y;
            mB[2*t] = v.x; mB[2*t+1] = v.y;
        }
    }
    {
        const float* ub = PB + P_SU + i*UST;            // stride 27: conflict-free LDS
        const float xA0 = sxB[jA*3+0], xA1 = sxB[jA*3+1], xA2 = sxB[jA*3+2];
        const float xB0 = sxB[jB*3+0], xB1 = sxB[jB*3+1], xB2 = sxB[jB*3+2];
#pragma unroll
        for (int c = 0; c < C1; ++c){
            float uu = ub[c];
            float4 wb = *(const float4*)(const void*)(cWB4 + c*4);   // constant port
            float hA = fsilu(fmaf(dA, wb.w, fmaf(xA2, wb.z,
                             fmaf(xA1, wb.y, fmaf(xA0, wb.x, uu)))));
            float hB = fsilu(fmaf(dB, wb.w, fmaf(xB2, wb.z,
                             fmaf(xB1, wb.y, fmaf(xB0, wb.x, uu)))));
            ull hsA = splat2(hA);
            ull hsB = splat2(hB);
            const ulonglong2* wr = (const ulonglong2*)(const void*)(cWE2 + c*MM);
#pragma unroll
            for (int t = 0; t < 8; ++t){
                ulonglong2 ww = wr[t];                               // constant port
                ffma2(mA[2*t],   hsA, ww.x);
                ffma2(mA[2*t+1], hsA, ww.y);
                ffma2(mB[2*t],   hsB, ww.x);
                ffma2(mB[2*t+1], hsB, ww.y);
            }
        }
    }

    // ---- epilogue: silu + gate (constant Wg), pair-sum, store ----
    {
        float fA[MM], fB[MM];
        float gA = cBG[0], gB = gA;
        const float4* wg4 = (const float4*)(const void*)cWG;
#pragma unroll
        for (int q = 0; q < 8; ++q){
            float4 wg = wg4[q];
            float2 fa0 = unpack2(mA[2*q]);
            float2 fa1 = unpack2(mA[2*q+1]);
            float2 fb0 = unpack2(mB[2*q]);
            float2 fb1 = unpack2(mB[2*q+1]);
            float a0 = fsilu(fa0.x), a1 = fsilu(fa0.y), a2 = fsilu(fa1.x), a3 = fsilu(fa1.y);
            float b0v = fsilu(fb0.x), b1v = fsilu(fb0.y), b2v = fsilu(fb1.x), b3v = fsilu(fb1.y);
            gA += a0*wg.x + a1*wg.y + a2*wg.z + a3*wg.w;
            gB += b0v*wg.x + b1v*wg.y + b2v*wg.z + b3v*wg.w;
            fA[4*q+0] = a0; fA[4*q+1] = a1; fA[4*q+2] = a2; fA[4*q+3] = a3;
            fB[4*q+0] = b0v; fB[4*q+1] = b1v; fB[4*q+2] = b2v; fB[4*q+3] = b3v;
        }
        gA = fsigmoid(gA);
        gB = fsigmoid(gB);
        float4* orow = (float4*)(PB + P_SMP + (pr*32 + node)*EROW);
#pragma unroll
        for (int t = 0; t < 8; ++t){
            float4 o;
            o.x = fA[4*t+0]*gA + fB[4*t+0]*gB;
            o.y = fA[4*t+1]*gA + fB[4*t+1]*gB;
            o.z = fA[4*t+2]*gA + fB[4*t+2]*gB;
            o.w = fA[4*t+3]*gA + fB[4*t+3]*gB;
            orow[t] = o;
        }
    }
    __syncthreads();   // P_SMP complete; su region now reusable

    // ================= node MLP: per batch, its 96 threads; trio per node =================
    {
        const int t96   = tid - s*96;       // 0..95 within this batch's warps
        const int node2 = t96 / 3;          // 0..31
        const int t3    = t96 % 3;
        float msum[MM];
        float4* ms4 = (float4*)msum;
#pragma unroll
        for (int t = 0; t < 8; ++t) ms4[t] = make_float4(0.f, 0.f, 0.f, 0.f);
#pragma unroll
        for (int e = 0; e < 3; ++e){
            const float4* rr = (const float4*)(PB + P_SMP + (e*32 + node2)*EROW);
#pragma unroll
            for (int t = 0; t < 8; ++t){
                float4 v = rr[t];
                ms4[t].x += v.x; ms4[t].y += v.y; ms4[t].z += v.z; ms4[t].w += v.w;
            }
        }
        const float y0 = sxB[node2*3+0], y1 = sxB[node2*3+1], y2 = sxB[node2*3+2];
        float h4[4];
#pragma unroll
        for (int k = 0; k < 4; ++k){
            int c = t3*4 + k;
            const float* row = sm + W_WN1F + c*NROW;
            float acc = sm[W_BN1 + c] + y0*row[0] + y1*row[1] + y2*row[2];
            const float4* rw = (const float4*)(row + 4);
#pragma unroll
            for (int t = 0; t < 8; ++t){
                float4 wv = rw[t];
                acc += msum[4*t+0]*wv.x; acc += msum[4*t+1]*wv.y;
                acc += msum[4*t+2]*wv.z; acc += msum[4*t+3]*wv.w;
            }
            h4[k] = fsilu(acc);
        }
        __syncthreads();
#pragma unroll
        for (int k = 0; k < 4; ++k)
            PB[P_SH12 + node2*H2 + t3*4 + k] = h4[k];
        __syncthreads();

        // 12 -> 6 + residual: 2 outputs per trio-thread
        if (node2 < NN){
#pragma unroll
            for (int oo = 0; oo < 2; ++oo){
                int o = t3*2 + oo;
                float acc = sm[W_BN2 + o];
#pragma unroll
                for (int c = 0; c < H2; ++c)
                    acc += PB[P_SH12 + node2*H2 + c] * sm[W_WN2 + c*6 + o];
                float base = (o % 3 == 0) ? y0 : ((o % 3 == 1) ? y1 : y2);
                PB[P_SFO + node2*6 + o] = acc + base;
            }
        }
    }
    __syncthreads();

    // ================= pool + head (warp pr==0 of each batch slot) =================
    if (pr == 0){
        const int pl = lane;
        const int bb = min(b0 + s, Btot - 1);
        float pool[6];
#pragma unroll
        for (int o = 0; o < 6; ++o) pool[o] = (pl < NN) ? PB[P_SFO + pl*6 + o] : 0.0f;
#pragma unroll
        for (int o = 0; o < 6; ++o){
#pragma unroll
            for (int off = 16; off > 0; off >>= 1)
                pool[o] += __shfl_xor_sync(0xffffffffu, pool[o], off);
            pool[o] *= (1.0f / 29.0f);
        }
        float hid = sm[W_BM1 + pl];
#pragma unroll
        for (int c = 0; c < 6; ++c) hid += pool[c] * sm[W_WM1 + c*MM + pl];
        hid = fmaxf(hid, 0.0f);
        PB[P_SHID + pl] = hid;
        __syncwarp();
        if (pl < H2){
            float acc = sm[W_BM2 + pl];
#pragma unroll
            for (int h = 0; h < MM; ++h) acc += PB[P_SHID + h] * sm[W_WM2 + h*H2 + pl];
            out[(size_t)bb*(NN*6) + pl] = acc;
        }
    }
    // zero-fill rows 2..28 for all 4 batches
    for (int t = tid; t < NB*NN*6; t += TPB){
        int ss = t / (NN*6), r = t % (NN*6);
        if (r >= H2){
            int bb = min(b0 + ss, Btot - 1);
            out[(size_t)bb*(NN*6) + r] = 0.0f;
        }
    }
}

extern "C" void kernel_launch(void* const* d_in, const int* in_sizes, int n_in,
                              void* d_out, int out_size)
{
    const float* x   = (const float*)d_in[0];
    // d_in[1] = mask (all-true in this problem)
    const float* We1 = (const float*)d_in[2];
    const float* be1 = (const float*)d_in[3];
    const float* We2 = (const float*)d_in[4];
    const float* be2 = (const float*)d_in[5];
    const float* Wg  = (const float*)d_in[6];
    const float* bg  = (const float*)d_in[7];
    const float* Wn1 = (const float*)d_in[8];
    const float* bn1 = (const float*)d_in[9];
    const float* Wn2 = (const float*)d_in[10];
    const float* bn2 = (const float*)d_in[11];
    const float* Wm1 = (const float*)d_in[12];
    const float* bm1 = (const float*)d_in[13];
    const float* Wm2 = (const float*)d_in[14];
    const float* bm2 = (const float*)d_in[15];

    int B = in_sizes[0] / (NN*3);
    cudaFuncSetAttribute(arnet_kernel, cudaFuncAttributeMaxDynamicSharedMemorySize, SMEM_BYTES);

    // stage raw weight tables into constant memory (async D2D memcpys, graph-capturable)
    cudaMemcpyToSymbolAsync(cWE2, We2, C1*MM*sizeof(float), 0, cudaMemcpyDeviceToDevice, 0);
    cudaMemcpyToSymbolAsync(cBE2, be2, MM*sizeof(float),   0, cudaMemcpyDeviceToDevice, 0);
    cudaMemcpyToSymbolAsync(cWG,  Wg,  MM*sizeof(float),   0, cudaMemcpyDeviceToDevice, 0);
    cudaMemcpyToSymbolAsync(cBG,  bg,  sizeof(float),      0, cudaMemcpyDeviceToDevice, 0);
    // folded WB4: prep kernel -> device scratch -> constant symbol
    arnet_prep<<<1, 128>>>(We1);
    void* wb4_addr = nullptr;
    cudaGetSymbolAddress(&wb4_addr, g_wb4);
    cudaMemcpyToSymbolAsync(cWB4, wb4_addr, C1*4*sizeof(float), 0, cudaMemcpyDeviceToDevice, 0);

    int grid = (B + NB - 1) / NB;
    arnet_kernel<<<grid, TPB, SMEM_BYTES>>>(x, We1, be1,
                                            Wn1, bn1, Wn2, bn2, Wm1, bm1, Wm2, bm2,
                                            (float*)d_out, B);
}